// round 11
// baseline (speedup 1.0000x reference)
#include <cstdint>
#include <cuda_runtime.h>
#include <cuda_bf16.h>

#define NH   6
#define HS   24
#define NE   144
#define TT   128
#define BB   256
#define MTOT (BB*TT)        // 32768 tokens

typedef __nv_bfloat16 bf16;

// ---------------- device scratch (allocation-free, bf16 hi/lo pairs) --------
__device__ bf16 g_qhi[MTOT*NE], g_qlo[MTOT*NE];
__device__ bf16 g_khi[MTOT*NE], g_klo[MTOT*NE];   // pre-scaled by 1/sqrt(hs)
__device__ bf16 g_vhi[MTOT*NE], g_vlo[MTOT*NE];
__device__ bf16 g_chi[MTOT*NE], g_clo[MTOT*NE];   // ctx, split
__device__ bf16 g_wthi[4*NE*NE], g_wtlo[4*NE*NE]; // W^T [n][k], q,k,v,proj
__device__ bf16 g_rhi[255*HS],   g_rlo[255*HS];   // rel_table split

// ---------------- helpers ----------------
__device__ __forceinline__ void mma_bf16(float c[4],
    uint32_t a0, uint32_t a1, uint32_t a2, uint32_t a3,
    uint32_t b0, uint32_t b1)
{
    asm volatile(
        "mma.sync.aligned.m16n8k16.row.col.f32.bf16.bf16.f32 "
        "{%0,%1,%2,%3}, {%4,%5,%6,%7}, {%8,%9}, {%0,%1,%2,%3};"
        : "+f"(c[0]), "+f"(c[1]), "+f"(c[2]), "+f"(c[3])
        : "r"(a0), "r"(a1), "r"(a2), "r"(a3), "r"(b0), "r"(b1));
}

__device__ __forceinline__ void split2(float v0, float v1, uint32_t& hi, uint32_t& lo)
{
    bf16 h0 = __float2bfloat16(v0), h1 = __float2bfloat16(v1);
    float r0 = v0 - __bfloat162float(h0), r1 = v1 - __bfloat162float(h1);
    hi = ((uint32_t)__bfloat16_as_ushort(h1) << 16) | __bfloat16_as_ushort(h0);
    lo = ((uint32_t)__bfloat16_as_ushort(__float2bfloat16(r1)) << 16)
       |  (uint32_t)__bfloat16_as_ushort(__float2bfloat16(r0));
}

__device__ __forceinline__ void cp_async8(uint32_t dst_smem, const void* src)
{
    asm volatile("cp.async.ca.shared.global [%0], [%1], 8;"
                 :: "r"(dst_smem), "l"(src));
}
#define CP_COMMIT() asm volatile("cp.async.commit_group;")
#define CP_WAIT0()  asm volatile("cp.async.wait_group 0;" ::: "memory")

// =====================================================================
// Setup: weight transpose+split and rel_table split (small)
// =====================================================================
__global__ __launch_bounds__(256) void split_wr_kernel(
    const float* __restrict__ Wq, const float* __restrict__ Wk,
    const float* __restrict__ Wv, const float* __restrict__ Wp,
    const float* __restrict__ rel)
{
    int m = blockIdx.y;
    int i = blockIdx.x * 256 + threadIdx.x;
    if (m < 4) {
        if (i >= NE * NE) return;
        const float* src = (m == 0) ? Wq : (m == 1) ? Wk : (m == 2) ? Wv : Wp;
        int k = i / NE, n = i - k * NE;
        float v = src[i];
        bf16 h = __float2bfloat16(v);
        g_wthi[m * NE * NE + n * NE + k] = h;
        g_wtlo[m * NE * NE + n * NE + k] = __float2bfloat16(v - __bfloat162float(h));
    } else {
        if (i >= 255 * HS) return;
        float v = rel[i];
        bf16 h = __float2bfloat16(v);
        g_rhi[i] = h;
        g_rlo[i] = __float2bfloat16(v - __bfloat162float(h));
    }
}

// =====================================================================
// GEMM v3: cp.async double-buffered, row stride 52 (conflict-free frags).
// smem byte layout per buffer parity p:
//   Ah(p)=p*26624  Al(p)=p*26624+13312        (A array: 128*52*2 = 13312 B)
//   Bh(p)=53248+p*29952  Bl(p)=+14976          (B array: 144*52*2 = 14976 B)
// total 113152 B -> 2 CTAs/SM.
// =====================================================================
#define LD3 52
#define GSM3 113152

__device__ __forceinline__ void gemm3_core(
    const float* __restrict__ Afp,
    const bf16* __restrict__ Ahig, const bf16* __restrict__ Alog,
    const bf16* __restrict__ Wthi, const bf16* __restrict__ Wtlo,
    int r0, float oscale, bf16* ohi, bf16* olo,
    float* ofp, const float* __restrict__ bias)
{
    extern __shared__ __align__(16) char smc[];
    const uint32_t sb = (uint32_t)__cvta_generic_to_shared(smc);
    const int tid = threadIdx.x;

    // ---- async loaders ----
    auto loadB = [&](int kc, int pb) {
        uint32_t dh = sb + 53248 + pb * 29952;
        uint32_t dl = dh + 14976;
        for (int i = tid; i < 144 * 12; i += 256) {
            int r = i / 12, j = i - r * 12;
            cp_async8(dh + r * 104 + j * 8, (const char*)(Wthi + r * NE + kc) + j * 8);
            cp_async8(dl + r * 104 + j * 8, (const char*)(Wtlo + r * NE + kc) + j * 8);
        }
    };
    auto loadA_pre = [&](int kc, int pb) {
        uint32_t dh = sb + pb * 26624;
        uint32_t dl = dh + 13312;
        for (int i = tid; i < 128 * 12; i += 256) {
            int r = i / 12, j = i - r * 12;
            cp_async8(dh + r * 104 + j * 8, (const char*)(Ahig + (r0 + r) * NE + kc) + j * 8);
            cp_async8(dl + r * 104 + j * 8, (const char*)(Alog + (r0 + r) * NE + kc) + j * 8);
        }
    };
    auto loadA_split = [&](int kc, int pb) {   // fp32 -> split, synchronous STS
        bf16* dh = (bf16*)(smc + pb * 26624);
        bf16* dl = (bf16*)(smc + pb * 26624 + 13312);
        for (int i = tid; i < 128 * 12; i += 256) {
            int r = i / 12, j = i - r * 12;
            float4 v = *(const float4*)&Afp[(r0 + r) * NE + kc + j * 4];
            uint32_t h0, l0, h1, l1;
            split2(v.x, v.y, h0, l0);
            split2(v.z, v.w, h1, l1);
            *(uint32_t*)&dh[r * LD3 + j * 4]     = h0;
            *(uint32_t*)&dh[r * LD3 + j * 4 + 2] = h1;
            *(uint32_t*)&dl[r * LD3 + j * 4]     = l0;
            *(uint32_t*)&dl[r * LD3 + j * 4 + 2] = l1;
        }
    };

    const int w = tid >> 5, lane = tid & 31, g = lane >> 2, t = lane & 3;
    const int mrow = (w & 3) * 32, ncol = (w >> 2) * 72;

    float acc[2][9][4];
    #pragma unroll
    for (int mt = 0; mt < 2; ++mt)
        #pragma unroll
        for (int nt = 0; nt < 9; ++nt)
            #pragma unroll
            for (int j = 0; j < 4; ++j) acc[mt][nt][j] = 0.f;

    // ---- prologue: chunk 0 into parity 0 ----
    loadB(0, 0);
    if (!Afp) loadA_pre(0, 0);
    CP_COMMIT();
    if (Afp) loadA_split(0, 0);
    CP_WAIT0();
    __syncthreads();

    // ---- pipelined chunk loop ----
    #pragma unroll 1
    for (int c = 0; c < 3; ++c) {
        const int cur = c & 1, nxt = cur ^ 1;
        if (c < 2) {
            loadB((c + 1) * 48, nxt);
            if (!Afp) loadA_pre((c + 1) * 48, nxt);
            CP_COMMIT();
        }

        #pragma unroll 1
        for (int p = 0; p < 3; ++p) {
            const bf16* Ap = (const bf16*)(smc + cur * 26624 + ((p == 1) ? 13312 : 0));
            const bf16* Bp = (const bf16*)(smc + 53248 + cur * 29952 + ((p == 2) ? 14976 : 0));
            #pragma unroll
            for (int ks = 0; ks < 3; ++ks) {
                const int k0 = ks * 16;
                uint32_t a[2][4];
                #pragma unroll
                for (int mt = 0; mt < 2; ++mt) {
                    const bf16* ab = Ap + (mrow + mt * 16 + g) * LD3 + k0 + 2 * t;
                    a[mt][0] = *(const uint32_t*)(ab);
                    a[mt][1] = *(const uint32_t*)(ab + 8 * LD3);
                    a[mt][2] = *(const uint32_t*)(ab + 8);
                    a[mt][3] = *(const uint32_t*)(ab + 8 * LD3 + 8);
                }
                #pragma unroll
                for (int nt = 0; nt < 9; ++nt) {
                    const bf16* bb = Bp + (ncol + nt * 8 + g) * LD3 + k0 + 2 * t;
                    uint32_t b0 = *(const uint32_t*)(bb);
                    uint32_t b1 = *(const uint32_t*)(bb + 8);
                    mma_bf16(acc[0][nt], a[0][0], a[0][1], a[0][2], a[0][3], b0, b1);
                    mma_bf16(acc[1][nt], a[1][0], a[1][1], a[1][2], a[1][3], b0, b1);
                }
            }
        }

        if (Afp && c < 2) loadA_split((c + 1) * 48, nxt);
        if (c < 2) CP_WAIT0();
        __syncthreads();
    }

    #pragma unroll
    for (int mt = 0; mt < 2; ++mt) {
        #pragma unroll
        for (int nt = 0; nt < 9; ++nt) {
            int row = r0 + mrow + mt * 16 + g;
            int col = ncol + nt * 8 + 2 * t;
            if (ofp) {
                float b0v = bias[col], b1v = bias[col + 1];
                ofp[row * NE + col]           = acc[mt][nt][0] + b0v;
                ofp[row * NE + col + 1]       = acc[mt][nt][1] + b1v;
                ofp[(row + 8) * NE + col]     = acc[mt][nt][2] + b0v;
                ofp[(row + 8) * NE + col + 1] = acc[mt][nt][3] + b1v;
            } else {
                uint32_t h, l;
                split2(acc[mt][nt][0] * oscale, acc[mt][nt][1] * oscale, h, l);
                *(uint32_t*)&ohi[row * NE + col] = h;
                *(uint32_t*)&olo[row * NE + col] = l;
                split2(acc[mt][nt][2] * oscale, acc[mt][nt][3] * oscale, h, l);
                *(uint32_t*)&ohi[(row + 8) * NE + col] = h;
                *(uint32_t*)&olo[(row + 8) * NE + col] = l;
            }
        }
    }
}

__global__ __launch_bounds__(256, 2) void qkv3_kernel(const float* __restrict__ x)
{
    const int z = blockIdx.y;
    const bf16* wh = g_wthi + z * NE * NE;
    const bf16* wl = g_wtlo + z * NE * NE;
    bf16 *oh, *ol;
    float sc = 1.f;
    if (z == 0)      { oh = g_qhi; ol = g_qlo; }
    else if (z == 1) { oh = g_khi; ol = g_klo; sc = 0.2041241452319315f; }
    else             { oh = g_vhi; ol = g_vlo; }
    gemm3_core(x, nullptr, nullptr, wh, wl, blockIdx.x * 128, sc, oh, ol, nullptr, nullptr);
}

__global__ __launch_bounds__(256, 2) void proj3_kernel(
    const float* __restrict__ bias, float* __restrict__ out)
{
    gemm3_core(nullptr, g_chi, g_clo, g_wthi + 3 * NE * NE, g_wtlo + 3 * NE * NE,
               blockIdx.x * 128, 1.f, nullptr, nullptr, out, bias);
}

// =====================================================================
// Attention v6: register-resident S + smem-staged K/R hi/lo.
// smem (bytes): P[128][132]f32 @0 (67584) | Vt hi/lo [24][136] (13056)
//   | Ksth @80640 | Kstl @87808 | Rsth @94976 | Rstl @102144  ([128][28] each)
// total 109312 B -> 2 CTAs/SM, 256 threads.
// =====================================================================
#define VLD   136
#define SLD   132
#define KLD   28
#define ASMEM6 109312

__global__ __launch_bounds__(256, 2) void attn6_kernel()
{
    extern __shared__ __align__(16) char smc[];
    float* P   = (float*)smc;
    bf16* Vthi = (bf16*)(smc + 67584);
    bf16* Vtlo = Vthi + 24 * VLD;
    bf16* Ksth = (bf16*)(smc + 80640);
    bf16* Kstl = (bf16*)(smc + 87808);
    bf16* Rsth = (bf16*)(smc + 94976);
    bf16* Rstl = (bf16*)(smc + 102144);

    const int bh = blockIdx.x;
    const int b = bh / NH, h = bh % NH;
    const int base = b * (TT * NE) + h * (TT * HS); // contiguous head chunk
    const int tid = threadIdx.x;

    // ---- stage V (transposed) and K/R (row-major, stride 28) ----
    {
        const int row = tid >> 1, half = (tid & 1) * 12;
        const int src = base + row * HS + half;
        #pragma unroll
        for (int j = 0; j < 12; ++j) {
            Vthi[(half + j) * VLD + row] = g_vhi[src + j];
            Vtlo[(half + j) * VLD + row] = g_vlo[src + j];
        }
        const bf16* gs[4] = {g_khi + base, g_klo + base, g_rhi + 127 * HS, g_rlo + 127 * HS};
        bf16* sd[4] = {Ksth, Kstl, Rsth, Rstl};
        #pragma unroll
        for (int rep = 0; rep < 6; ++rep) {
            int i = rep * 256 + tid;           // 0..1535
            int arr = i / 384, rem = i - arr * 384;
            int r = rem / 3, j = rem - r * 3;  // row, 8-elt segment
            uint4 v = *(const uint4*)&gs[arr][r * HS + j * 8];
            *(uint2*)&sd[arr][r * KLD + j * 8]     = make_uint2(v.x, v.y);
            *(uint2*)&sd[arr][r * KLD + j * 8 + 4] = make_uint2(v.z, v.w);
        }
    }
    __syncthreads();   // the only block barrier

    const int w = tid >> 5, lane = tid & 31, g = lane >> 2, t = lane & 3;
    const int tr  = w * 16 + g;       // warp owns rows w*16 .. w*16+15
    const int tr2 = tr + 8;

    float acc[16][4];

    // ---- pass 1: acc = P = Q @ R^T for own rows ----
    #pragma unroll
    for (int nt = 0; nt < 16; ++nt)
        #pragma unroll
        for (int j = 0; j < 4; ++j) acc[nt][j] = 0.f;

    #pragma unroll 1
    for (int p = 0; p < 3; ++p) {
        const bf16* Ag = ((p == 1) ? g_qlo : g_qhi) + base;
        const bf16* Bs = (p == 2) ? Rstl : Rsth;
        const bf16* ab = Ag + tr * HS + 2 * t;
        uint32_t a0 = *(const uint32_t*)(ab);
        uint32_t a1 = *(const uint32_t*)(ab + 8 * HS);
        uint32_t a2 = *(const uint32_t*)(ab + 8);
        uint32_t a3 = *(const uint32_t*)(ab + 8 * HS + 8);
        uint32_t a4 = *(const uint32_t*)(ab + 16);
        uint32_t a5 = *(const uint32_t*)(ab + 8 * HS + 16);
        #pragma unroll
        for (int nt = 0; nt < 16; ++nt) {
            const bf16* bb = Bs + (nt * 8 + g) * KLD + 2 * t;
            uint32_t b0 = *(const uint32_t*)(bb);
            uint32_t b1 = *(const uint32_t*)(bb + 8);
            uint32_t b2 = *(const uint32_t*)(bb + 16);
            mma_bf16(acc[nt], a0, a1, a2, a3, b0, b1);
            mma_bf16(acc[nt], a4, a5, 0u, 0u, b2, 0u);
        }
    }
    #pragma unroll
    for (int nt = 0; nt < 16; ++nt) {
        *(float2*)&P[tr  * SLD + nt * 8 + 2 * t] = make_float2(acc[nt][0], acc[nt][1]);
        *(float2*)&P[tr2 * SLD + nt * 8 + 2 * t] = make_float2(acc[nt][2], acc[nt][3]);
    }
    __syncwarp();      // P rows are warp-private

    // ---- pass 2: acc = S = Q @ K'^T ----
    #pragma unroll
    for (int nt = 0; nt < 16; ++nt)
        #pragma unroll
        for (int j = 0; j < 4; ++j) acc[nt][j] = 0.f;

    #pragma unroll 1
    for (int p = 0; p < 3; ++p) {
        const bf16* Ag = ((p == 1) ? g_qlo : g_qhi) + base;
        const bf16* Bs = (p == 2) ? Kstl : Ksth;
        const bf16* ab = Ag + tr * HS + 2 * t;
        uint32_t a0 = *(const uint32_t*)(ab);
        uint32_t a1 = *(const uint32_t*)(ab + 8 * HS);
        uint32_t a2 = *(const uint32_t*)(ab + 8);
        uint32_t a3 = *(const uint32_t*)(ab + 8 * HS + 8);
        uint32_t a4 = *(const uint32_t*)(ab + 16);
        uint32_t a5 = *(const uint32_t*)(ab + 8 * HS + 16);
        #pragma unroll
        for (int nt = 0; nt < 16; ++nt) {
            const bf16* bb = Bs + (nt * 8 + g) * KLD + 2 * t;
            uint32_t b0 = *(const uint32_t*)(bb);
            uint32_t b1 = *(const uint32_t*)(bb + 8);
            uint32_t b2 = *(const uint32_t*)(bb + 16);
            mma_bf16(acc[nt], a0, a1, a2, a3, b0, b1);
            mma_bf16(acc[nt], a4, a5, 0u, 0u, b2, 0u);
        }
    }

    // ---- rel gather + causal mask (register-resident) ----
    #pragma unroll
    for (int nt = 0; nt < 16; ++nt) {
        int c = nt * 8 + 2 * t;
        acc[nt][0] = (c     <= tr ) ? acc[nt][0] + P[tr  * SLD + tr  - c    ] : -1e30f;
        acc[nt][1] = (c + 1 <= tr ) ? acc[nt][1] + P[tr  * SLD + tr  - c - 1] : -1e30f;
        acc[nt][2] = (c     <= tr2) ? acc[nt][2] + P[tr2 * SLD + tr2 - c    ] : -1e30f;
        acc[nt][3] = (c + 1 <= tr2) ? acc[nt][3] + P[tr2 * SLD + tr2 - c - 1] : -1e30f;
    }

    // ---- softmax in registers (t-group reduction) ----
    {
        float m1 = -1e30f, m2 = -1e30f;
        #pragma unroll
        for (int nt = 0; nt < 16; ++nt) {
            m1 = fmaxf(m1, fmaxf(acc[nt][0], acc[nt][1]));
            m2 = fmaxf(m2, fmaxf(acc[nt][2], acc[nt][3]));
        }
        m1 = fmaxf(m1, __shfl_xor_sync(0xffffffffu, m1, 1));
        m1 = fmaxf(m1, __shfl_xor_sync(0xffffffffu, m1, 2));
        m2 = fmaxf(m2, __shfl_xor_sync(0xffffffffu, m2, 1));
        m2 = fmaxf(m2, __shfl_xor_sync(0xffffffffu, m2, 2));
        float s1 = 0.f, s2 = 0.f;
        #pragma unroll
        for (int nt = 0; nt < 16; ++nt) {
            acc[nt][0] = __expf(acc[nt][0] - m1);  s1 += acc[nt][0];
            acc[nt][1] = __expf(acc[nt][1] - m1);  s1 += acc[nt][1];
            acc[nt][2] = __expf(acc[nt][2] - m2);  s2 += acc[nt][2];
            acc[nt][3] = __expf(acc[nt][3] - m2);  s2 += acc[nt][3];
        }
        s1 += __shfl_xor_sync(0xffffffffu, s1, 1);
        s1 += __shfl_xor_sync(0xffffffffu, s1, 2);
        s2 += __shfl_xor_sync(0xffffffffu, s2, 1);
        s2 += __shfl_xor_sync(0xffffffffu, s2, 2);
        float i1 = 1.0f / s1, i2 = 1.0f / s2;
        #pragma unroll
        for (int nt = 0; nt < 16; ++nt) {
            acc[nt][0] *= i1;  acc[nt][1] *= i1;
            acc[nt][2] *= i2;  acc[nt][3] *= i2;
        }
    }

    // ---- ctx = S @ V: acc tiles ARE the A-fragments ----
    {
        float cacc[3][4];
        #pragma unroll
        for (int nt = 0; nt < 3; ++nt)
            #pragma unroll
            for (int j = 0; j < 4; ++j) cacc[nt][j] = 0.f;

        #pragma unroll
        for (int ks = 0; ks < 8; ++ks) {
            const int k0 = ks * 16;
            uint32_t ah0, al0, ah1, al1, ah2, al2, ah3, al3;
            split2(acc[2*ks][0],   acc[2*ks][1],   ah0, al0);
            split2(acc[2*ks][2],   acc[2*ks][3],   ah1, al1);
            split2(acc[2*ks+1][0], acc[2*ks+1][1], ah2, al2);
            split2(acc[2*ks+1][2], acc[2*ks+1][3], ah3, al3);
            #pragma unroll
            for (int nt = 0; nt < 3; ++nt) {
                const bf16* bhp = Vthi + (nt * 8 + g) * VLD + k0 + 2 * t;
                const bf16* blp = Vtlo + (nt * 8 + g) * VLD + k0 + 2 * t;
                uint32_t bh0 = *(const uint32_t*)(bhp);
                uint32_t bh1 = *(const uint32_t*)(bhp + 8);
                uint32_t bl0 = *(const uint32_t*)(blp);
                uint32_t bl1 = *(const uint32_t*)(blp + 8);
                mma_bf16(cacc[nt], ah0, ah1, ah2, ah3, bh0, bh1);
                mma_bf16(cacc[nt], al0, al1, al2, al3, bh0, bh1);
                mma_bf16(cacc[nt], ah0, ah1, ah2, ah3, bl0, bl1);
            }
        }

        #pragma unroll
        for (int nt = 0; nt < 3; ++nt) {
            int col = nt * 8 + 2 * t;
            int idx = b * (TT * NE) + tr * NE + h * HS + col;
            uint32_t hp, lp;
            split2(cacc[nt][0], cacc[nt][1], hp, lp);
            *(uint32_t*)&g_chi[idx] = hp;
            *(uint32_t*)&g_clo[idx] = lp;
            split2(cacc[nt][2], cacc[nt][3], hp, lp);
            *(uint32_t*)&g_chi[idx + 8 * NE] = hp;
            *(uint32_t*)&g_clo[idx + 8 * NE] = lp;
        }
    }
}

// =====================================================================
extern "C" void kernel_launch(void* const* d_in, const int* in_sizes, int n_in,
                              void* d_out, int out_size)
{
    const float* x   = (const float*)d_in[0];
    const float* Wq  = (const float*)d_in[1];
    const float* Wk  = (const float*)d_in[2];
    const float* Wv  = (const float*)d_in[3];
    const float* rel = (const float*)d_in[4];
    const float* Wp  = (const float*)d_in[5];
    const float* bp  = (const float*)d_in[6];
    float* out = (float*)d_out;

    cudaFuncSetAttribute(qkv3_kernel,
                         cudaFuncAttributeMaxDynamicSharedMemorySize, GSM3);
    cudaFuncSetAttribute(proj3_kernel,
                         cudaFuncAttributeMaxDynamicSharedMemorySize, GSM3);
    cudaFuncSetAttribute(attn6_kernel,
                         cudaFuncAttributeMaxDynamicSharedMemorySize, ASMEM6);

    split_wr_kernel<<<dim3(81, 5), 256>>>(Wq, Wk, Wv, Wp, rel);

    dim3 gQ(MTOT / 128, 3);
    qkv3_kernel<<<gQ, 256, GSM3>>>(x);

    attn6_kernel<<<BB * NH, 256, ASMEM6>>>();

    proj3_kernel<<<MTOT / 128, 256, GSM3>>>(bp, out);
}

// round 12
// speedup vs baseline: 1.1754x; 1.1754x over previous
#include <cstdint>
#include <cuda_runtime.h>
#include <cuda_bf16.h>

#define NH   6
#define HS   24
#define NE   144
#define TT   128
#define BB   256
#define MTOT (BB*TT)        // 32768 tokens

typedef __nv_bfloat16 bf16;

// ---------------- device scratch (allocation-free, bf16 hi/lo pairs) --------
__device__ bf16 g_qhi[MTOT*NE], g_qlo[MTOT*NE];
__device__ bf16 g_khi[MTOT*NE], g_klo[MTOT*NE];   // pre-scaled by 1/sqrt(hs)
__device__ bf16 g_vhi[MTOT*NE], g_vlo[MTOT*NE];
__device__ bf16 g_chi[MTOT*NE], g_clo[MTOT*NE];   // ctx, split
__device__ bf16 g_wthi[4*NE*NE], g_wtlo[4*NE*NE]; // W^T [n][k], q,k,v,proj
__device__ bf16 g_rhi[255*HS],   g_rlo[255*HS];   // rel_table split

// ---------------- helpers ----------------
__device__ __forceinline__ void mma_bf16(float c[4],
    uint32_t a0, uint32_t a1, uint32_t a2, uint32_t a3,
    uint32_t b0, uint32_t b1)
{
    asm volatile(
        "mma.sync.aligned.m16n8k16.row.col.f32.bf16.bf16.f32 "
        "{%0,%1,%2,%3}, {%4,%5,%6,%7}, {%8,%9}, {%0,%1,%2,%3};"
        : "+f"(c[0]), "+f"(c[1]), "+f"(c[2]), "+f"(c[3])
        : "r"(a0), "r"(a1), "r"(a2), "r"(a3), "r"(b0), "r"(b1));
}

__device__ __forceinline__ void split2(float v0, float v1, uint32_t& hi, uint32_t& lo)
{
    bf16 h0 = __float2bfloat16(v0), h1 = __float2bfloat16(v1);
    float r0 = v0 - __bfloat162float(h0), r1 = v1 - __bfloat162float(h1);
    hi = ((uint32_t)__bfloat16_as_ushort(h1) << 16) | __bfloat16_as_ushort(h0);
    lo = ((uint32_t)__bfloat16_as_ushort(__float2bfloat16(r1)) << 16)
       |  (uint32_t)__bfloat16_as_ushort(__float2bfloat16(r0));
}

// =====================================================================
// Setup: weight transpose+split and rel_table split (small)
// =====================================================================
__global__ __launch_bounds__(256) void split_wr_kernel(
    const float* __restrict__ Wq, const float* __restrict__ Wk,
    const float* __restrict__ Wv, const float* __restrict__ Wp,
    const float* __restrict__ rel)
{
    int m = blockIdx.y;
    int i = blockIdx.x * 256 + threadIdx.x;
    if (m < 4) {
        if (i >= NE * NE) return;
        const float* src = (m == 0) ? Wq : (m == 1) ? Wk : (m == 2) ? Wv : Wp;
        int k = i / NE, n = i - k * NE;
        float v = src[i];
        bf16 h = __float2bfloat16(v);
        g_wthi[m * NE * NE + n * NE + k] = h;
        g_wtlo[m * NE * NE + n * NE + k] = __float2bfloat16(v - __bfloat162float(h));
    } else {
        if (i >= 255 * HS) return;
        float v = rel[i];
        bf16 h = __float2bfloat16(v);
        g_rhi[i] = h;
        g_rlo[i] = __float2bfloat16(v - __bfloat162float(h));
    }
}

// =====================================================================
// qkv4: fused Q/K/V GEMM, A tile resident (split once), grid 256.
// smem: A_hi[128][152] | A_lo | B_hi[144][56] | B_lo   = 110080 B, 2 CTAs/SM
// =====================================================================
#define LDA4 152
#define LDS2 56
#define QSM4 (2*128*LDA4*2 + 2*144*LDS2*2)   // 110080

__global__ __launch_bounds__(256, 2) void qkv4_kernel(const float* __restrict__ x)
{
    extern __shared__ __align__(16) char smc[];
    bf16* A_hi = (bf16*)smc;                          // [128][152]
    bf16* A_lo = A_hi + 128 * LDA4;
    bf16* Bs_hi = A_lo + 128 * LDA4;                  // [144][56]
    bf16* Bs_lo = Bs_hi + 144 * LDS2;

    const int r0 = blockIdx.x * 128;
    const int tid = threadIdx.x;
    const int w = tid >> 5, lane = tid & 31, g = lane >> 2, t = lane & 3;
    const int mrow = (w & 3) * 32, ncol = (w >> 2) * 72;

    // ---- load + split A once (128 x 144 fp32 -> hi/lo bf16) ----
    for (int i = tid; i < 128 * 36; i += 256) {
        int r = i / 36, j = i - r * 36;
        float4 v = *(const float4*)&x[(r0 + r) * NE + j * 4];
        uint32_t h0, l0, h1, l1;
        split2(v.x, v.y, h0, l0);
        split2(v.z, v.w, h1, l1);
        *(uint32_t*)&A_hi[r * LDA4 + j * 4]     = h0;
        *(uint32_t*)&A_hi[r * LDA4 + j * 4 + 2] = h1;
        *(uint32_t*)&A_lo[r * LDA4 + j * 4]     = l0;
        *(uint32_t*)&A_lo[r * LDA4 + j * 4 + 2] = l1;
    }
    __syncthreads();

    #pragma unroll 1
    for (int z = 0; z < 3; ++z) {
        const bf16* Wthi = g_wthi + z * NE * NE;
        const bf16* Wtlo = g_wtlo + z * NE * NE;

        float acc[2][9][4];
        #pragma unroll
        for (int mt = 0; mt < 2; ++mt)
            #pragma unroll
            for (int nt = 0; nt < 9; ++nt)
                #pragma unroll
                for (int j = 0; j < 4; ++j) acc[mt][nt][j] = 0.f;

        #pragma unroll 1
        for (int kc = 0; kc < NE; kc += 48) {
            for (int i = tid; i < 144 * 6; i += 256) {
                int r = i / 6, j = i - r * 6;
                *(uint4*)&Bs_hi[r * LDS2 + j * 8] = *(const uint4*)&Wthi[r * NE + kc + j * 8];
                *(uint4*)&Bs_lo[r * LDS2 + j * 8] = *(const uint4*)&Wtlo[r * NE + kc + j * 8];
            }
            __syncthreads();

            #pragma unroll 1
            for (int p = 0; p < 3; ++p) {
                const bf16* Ap = (p == 1) ? A_lo : A_hi;
                const bf16* Bp = (p == 2) ? Bs_lo : Bs_hi;
                #pragma unroll
                for (int ks = 0; ks < 3; ++ks) {
                    const int ka = kc + ks * 16;     // absolute k into resident A
                    const int kb = ks * 16;          // local k into B chunk
                    uint32_t a[2][4];
                    #pragma unroll
                    for (int mt = 0; mt < 2; ++mt) {
                        const bf16* ab = Ap + (mrow + mt * 16 + g) * LDA4 + ka + 2 * t;
                        a[mt][0] = *(const uint32_t*)(ab);
                        a[mt][1] = *(const uint32_t*)(ab + 8 * LDA4);
                        a[mt][2] = *(const uint32_t*)(ab + 8);
                        a[mt][3] = *(const uint32_t*)(ab + 8 * LDA4 + 8);
                    }
                    #pragma unroll
                    for (int nt = 0; nt < 9; ++nt) {
                        const bf16* bb = Bp + (ncol + nt * 8 + g) * LDS2 + kb + 2 * t;
                        uint32_t b0 = *(const uint32_t*)(bb);
                        uint32_t b1 = *(const uint32_t*)(bb + 8);
                        mma_bf16(acc[0][nt], a[0][0], a[0][1], a[0][2], a[0][3], b0, b1);
                        mma_bf16(acc[1][nt], a[1][0], a[1][1], a[1][2], a[1][3], b0, b1);
                    }
                }
            }
            __syncthreads();
        }

        bf16* ohi = (z == 0) ? g_qhi : (z == 1) ? g_khi : g_vhi;
        bf16* olo = (z == 0) ? g_qlo : (z == 1) ? g_klo : g_vlo;
        const float sc = (z == 1) ? 0.2041241452319315f : 1.f;

        #pragma unroll
        for (int mt = 0; mt < 2; ++mt) {
            #pragma unroll
            for (int nt = 0; nt < 9; ++nt) {
                int row = r0 + mrow + mt * 16 + g;
                int col = ncol + nt * 8 + 2 * t;
                uint32_t h, l;
                split2(acc[mt][nt][0] * sc, acc[mt][nt][1] * sc, h, l);
                *(uint32_t*)&ohi[row * NE + col] = h;
                *(uint32_t*)&olo[row * NE + col] = l;
                split2(acc[mt][nt][2] * sc, acc[mt][nt][3] * sc, h, l);
                *(uint32_t*)&ohi[(row + 8) * NE + col] = h;
                *(uint32_t*)&olo[(row + 8) * NE + col] = l;
            }
        }
    }
}

// =====================================================================
// proj (R10-exact gemm2 core, validated 28.4us)
// =====================================================================
#define GSMEM ((128*LDS2 + 128*LDS2 + 144*LDS2 + 144*LDS2) * 2)   // 60928

__global__ __launch_bounds__(256, 2) void proj2_kernel(
    const float* __restrict__ bias, float* __restrict__ out)
{
    extern __shared__ __align__(16) char smc[];
    bf16* As_hi = (bf16*)smc;
    bf16* As_lo = As_hi + 128 * LDS2;
    bf16* Bs_hi = As_lo + 128 * LDS2;
    bf16* Bs_lo = Bs_hi + 144 * LDS2;

    const bf16* Ahig = g_chi;
    const bf16* Alog = g_clo;
    const bf16* Wthi = g_wthi + 3 * NE * NE;
    const bf16* Wtlo = g_wtlo + 3 * NE * NE;
    const int r0 = blockIdx.x * 128;

    const int tid = threadIdx.x;
    const int w = tid >> 5, lane = tid & 31, g = lane >> 2, t = lane & 3;
    const int mrow = (w & 3) * 32, ncol = (w >> 2) * 72;

    float acc[2][9][4];
    #pragma unroll
    for (int mt = 0; mt < 2; ++mt)
        #pragma unroll
        for (int nt = 0; nt < 9; ++nt)
            #pragma unroll
            for (int j = 0; j < 4; ++j) acc[mt][nt][j] = 0.f;

    #pragma unroll 1
    for (int kc = 0; kc < NE; kc += 48) {
        for (int i = tid; i < 128 * 6; i += 256) {
            int r = i / 6, j = i - r * 6;
            *(uint4*)&As_hi[r * LDS2 + j * 8] = *(const uint4*)&Ahig[(r0 + r) * NE + kc + j * 8];
            *(uint4*)&As_lo[r * LDS2 + j * 8] = *(const uint4*)&Alog[(r0 + r) * NE + kc + j * 8];
        }
        for (int i = tid; i < 144 * 6; i += 256) {
            int r = i / 6, j = i - r * 6;
            *(uint4*)&Bs_hi[r * LDS2 + j * 8] = *(const uint4*)&Wthi[r * NE + kc + j * 8];
            *(uint4*)&Bs_lo[r * LDS2 + j * 8] = *(const uint4*)&Wtlo[r * NE + kc + j * 8];
        }
        __syncthreads();

        #pragma unroll 1
        for (int p = 0; p < 3; ++p) {
            const bf16* Ap = (p == 1) ? As_lo : As_hi;
            const bf16* Bp = (p == 2) ? Bs_lo : Bs_hi;
            #pragma unroll
            for (int ks = 0; ks < 3; ++ks) {
                const int k0 = ks * 16;
                uint32_t a[2][4];
                #pragma unroll
                for (int mt = 0; mt < 2; ++mt) {
                    const bf16* ab = Ap + (mrow + mt * 16 + g) * LDS2 + k0 + 2 * t;
                    a[mt][0] = *(const uint32_t*)(ab);
                    a[mt][1] = *(const uint32_t*)(ab + 8 * LDS2);
                    a[mt][2] = *(const uint32_t*)(ab + 8);
                    a[mt][3] = *(const uint32_t*)(ab + 8 * LDS2 + 8);
                }
                #pragma unroll
                for (int nt = 0; nt < 9; ++nt) {
                    const bf16* bb = Bp + (ncol + nt * 8 + g) * LDS2 + k0 + 2 * t;
                    uint32_t b0 = *(const uint32_t*)(bb);
                    uint32_t b1 = *(const uint32_t*)(bb + 8);
                    mma_bf16(acc[0][nt], a[0][0], a[0][1], a[0][2], a[0][3], b0, b1);
                    mma_bf16(acc[1][nt], a[1][0], a[1][1], a[1][2], a[1][3], b0, b1);
                }
            }
        }
        __syncthreads();
    }

    #pragma unroll
    for (int mt = 0; mt < 2; ++mt) {
        #pragma unroll
        for (int nt = 0; nt < 9; ++nt) {
            int row = r0 + mrow + mt * 16 + g;
            int col = ncol + nt * 8 + 2 * t;
            float b0v = bias[col], b1v = bias[col + 1];
            out[row * NE + col]           = acc[mt][nt][0] + b0v;
            out[row * NE + col + 1]       = acc[mt][nt][1] + b1v;
            out[(row + 8) * NE + col]     = acc[mt][nt][2] + b0v;
            out[(row + 8) * NE + col + 1] = acc[mt][nt][3] + b1v;
        }
    }
}

// =====================================================================
// Attention v5 (R10-exact): warp-per-16-rows, register-resident S.
// =====================================================================
#define VLD   136     // Vt row stride (bf16)
#define SLD   132     // P row stride (fp32)
#define ASMEM5 (128*SLD*4 + 2*24*VLD*2)   // 80640 B

__global__ __launch_bounds__(256, 2) void attn5_kernel()
{
    extern __shared__ __align__(16) char smc[];
    float* P   = (float*)smc;                       // [128][132] fp32
    bf16* Vthi = (bf16*)(smc + 128 * SLD * 4);      // [24][136]
    bf16* Vtlo = Vthi + 24 * VLD;

    const int bh = blockIdx.x;
    const int b = bh / NH, h = bh % NH;
    const int base = b * (TT * NE) + h * (TT * HS); // contiguous head chunk
    const int tid = threadIdx.x;

    {   // V transpose into smem
        const int row = tid >> 1, half = (tid & 1) * 12;
        const int src = base + row * HS + half;
        #pragma unroll
        for (int j = 0; j < 12; ++j) {
            Vthi[(half + j) * VLD + row] = g_vhi[src + j];
            Vtlo[(half + j) * VLD + row] = g_vlo[src + j];
        }
    }
    __syncthreads();   // the only block barrier

    const int w = tid >> 5, lane = tid & 31, g = lane >> 2, t = lane & 3;
    const int tr  = w * 16 + g;
    const int tr2 = tr + 8;

    float acc[16][4];

    // ---- pass 1: acc = P = Q @ R^T ----
    #pragma unroll
    for (int nt = 0; nt < 16; ++nt)
        #pragma unroll
        for (int j = 0; j < 4; ++j) acc[nt][j] = 0.f;

    #pragma unroll 1
    for (int p = 0; p < 3; ++p) {
        const bf16* Ag = ((p == 1) ? g_qlo : g_qhi) + base;
        const bf16* Bg = ((p == 2) ? g_rlo : g_rhi) + 127 * HS;
        const bf16* ab = Ag + tr * HS + 2 * t;
        uint32_t a0 = *(const uint32_t*)(ab);
        uint32_t a1 = *(const uint32_t*)(ab + 8 * HS);
        uint32_t a2 = *(const uint32_t*)(ab + 8);
        uint32_t a3 = *(const uint32_t*)(ab + 8 * HS + 8);
        uint32_t a4 = *(const uint32_t*)(ab + 16);
        uint32_t a5 = *(const uint32_t*)(ab + 8 * HS + 16);
        #pragma unroll
        for (int nt = 0; nt < 16; ++nt) {
            const bf16* bb = Bg + (nt * 8 + g) * HS + 2 * t;
            uint32_t b0 = *(const uint32_t*)(bb);
            uint32_t b1 = *(const uint32_t*)(bb + 8);
            uint32_t b2 = *(const uint32_t*)(bb + 16);
            mma_bf16(acc[nt], a0, a1, a2, a3, b0, b1);
            mma_bf16(acc[nt], a4, a5, 0u, 0u, b2, 0u);
        }
    }
    #pragma unroll
    for (int nt = 0; nt < 16; ++nt) {
        *(float2*)&P[tr  * SLD + nt * 8 + 2 * t] = make_float2(acc[nt][0], acc[nt][1]);
        *(float2*)&P[tr2 * SLD + nt * 8 + 2 * t] = make_float2(acc[nt][2], acc[nt][3]);
    }
    __syncwarp();

    // ---- pass 2: acc = S = Q @ K'^T ----
    #pragma unroll
    for (int nt = 0; nt < 16; ++nt)
        #pragma unroll
        for (int j = 0; j < 4; ++j) acc[nt][j] = 0.f;

    #pragma unroll 1
    for (int p = 0; p < 3; ++p) {
        const bf16* Ag = ((p == 1) ? g_qlo : g_qhi) + base;
        const bf16* Bg = ((p == 2) ? g_klo : g_khi) + base;
        const bf16* ab = Ag + tr * HS + 2 * t;
        uint32_t a0 = *(const uint32_t*)(ab);
        uint32_t a1 = *(const uint32_t*)(ab + 8 * HS);
        uint32_t a2 = *(const uint32_t*)(ab + 8);
        uint32_t a3 = *(const uint32_t*)(ab + 8 * HS + 8);
        uint32_t a4 = *(const uint32_t*)(ab + 16);
        uint32_t a5 = *(const uint32_t*)(ab + 8 * HS + 16);
        #pragma unroll
        for (int nt = 0; nt < 16; ++nt) {
            const bf16* bb = Bg + (nt * 8 + g) * HS + 2 * t;
            uint32_t b0 = *(const uint32_t*)(bb);
            uint32_t b1 = *(const uint32_t*)(bb + 8);
            uint32_t b2 = *(const uint32_t*)(bb + 16);
            mma_bf16(acc[nt], a0, a1, a2, a3, b0, b1);
            mma_bf16(acc[nt], a4, a5, 0u, 0u, b2, 0u);
        }
    }

    // ---- rel gather + causal mask ----
    #pragma unroll
    for (int nt = 0; nt < 16; ++nt) {
        int c = nt * 8 + 2 * t;
        acc[nt][0] = (c     <= tr ) ? acc[nt][0] + P[tr  * SLD + tr  - c    ] : -1e30f;
        acc[nt][1] = (c + 1 <= tr ) ? acc[nt][1] + P[tr  * SLD + tr  - c - 1] : -1e30f;
        acc[nt][2] = (c     <= tr2) ? acc[nt][2] + P[tr2 * SLD + tr2 - c    ] : -1e30f;
        acc[nt][3] = (c + 1 <= tr2) ? acc[nt][3] + P[tr2 * SLD + tr2 - c - 1] : -1e30f;
    }

    // ---- softmax in registers ----
    {
        float m1 = -1e30f, m2 = -1e30f;
        #pragma unroll
        for (int nt = 0; nt < 16; ++nt) {
            m1 = fmaxf(m1, fmaxf(acc[nt][0], acc[nt][1]));
            m2 = fmaxf(m2, fmaxf(acc[nt][2], acc[nt][3]));
        }
        m1 = fmaxf(m1, __shfl_xor_sync(0xffffffffu, m1, 1));
        m1 = fmaxf(m1, __shfl_xor_sync(0xffffffffu, m1, 2));
        m2 = fmaxf(m2, __shfl_xor_sync(0xffffffffu, m2, 1));
        m2 = fmaxf(m2, __shfl_xor_sync(0xffffffffu, m2, 2));
        float s1 = 0.f, s2 = 0.f;
        #pragma unroll
        for (int nt = 0; nt < 16; ++nt) {
            acc[nt][0] = __expf(acc[nt][0] - m1);  s1 += acc[nt][0];
            acc[nt][1] = __expf(acc[nt][1] - m1);  s1 += acc[nt][1];
            acc[nt][2] = __expf(acc[nt][2] - m2);  s2 += acc[nt][2];
            acc[nt][3] = __expf(acc[nt][3] - m2);  s2 += acc[nt][3];
        }
        s1 += __shfl_xor_sync(0xffffffffu, s1, 1);
        s1 += __shfl_xor_sync(0xffffffffu, s1, 2);
        s2 += __shfl_xor_sync(0xffffffffu, s2, 1);
        s2 += __shfl_xor_sync(0xffffffffu, s2, 2);
        float i1 = 1.0f / s1, i2 = 1.0f / s2;
        #pragma unroll
        for (int nt = 0; nt < 16; ++nt) {
            acc[nt][0] *= i1;  acc[nt][1] *= i1;
            acc[nt][2] *= i2;  acc[nt][3] *= i2;
        }
    }

    // ---- ctx = S @ V ----
    {
        float cacc[3][4];
        #pragma unroll
        for (int nt = 0; nt < 3; ++nt)
            #pragma unroll
            for (int j = 0; j < 4; ++j) cacc[nt][j] = 0.f;

        #pragma unroll
        for (int ks = 0; ks < 8; ++ks) {
            const int k0 = ks * 16;
            uint32_t ah0, al0, ah1, al1, ah2, al2, ah3, al3;
            split2(acc[2*ks][0],   acc[2*ks][1],   ah0, al0);
            split2(acc[2*ks][2],   acc[2*ks][3],   ah1, al1);
            split2(acc[2*ks+1][0], acc[2*ks+1][1], ah2, al2);
            split2(acc[2*ks+1][2], acc[2*ks+1][3], ah3, al3);
            #pragma unroll
            for (int nt = 0; nt < 3; ++nt) {
                const bf16* bhp = Vthi + (nt * 8 + g) * VLD + k0 + 2 * t;
                const bf16* blp = Vtlo + (nt * 8 + g) * VLD + k0 + 2 * t;
                uint32_t bh0 = *(const uint32_t*)(bhp);
                uint32_t bh1 = *(const uint32_t*)(bhp + 8);
                uint32_t bl0 = *(const uint32_t*)(blp);
                uint32_t bl1 = *(const uint32_t*)(blp + 8);
                mma_bf16(cacc[nt], ah0, ah1, ah2, ah3, bh0, bh1);
                mma_bf16(cacc[nt], al0, al1, al2, al3, bh0, bh1);
                mma_bf16(cacc[nt], ah0, ah1, ah2, ah3, bl0, bl1);
            }
        }

        #pragma unroll
        for (int nt = 0; nt < 3; ++nt) {
            int col = nt * 8 + 2 * t;
            int idx = b * (TT * NE) + tr * NE + h * HS + col;
            uint32_t hp, lp;
            split2(cacc[nt][0], cacc[nt][1], hp, lp);
            *(uint32_t*)&g_chi[idx] = hp;
            *(uint32_t*)&g_clo[idx] = lp;
            split2(cacc[nt][2], cacc[nt][3], hp, lp);
            *(uint32_t*)&g_chi[idx + 8 * NE] = hp;
            *(uint32_t*)&g_clo[idx + 8 * NE] = lp;
        }
    }
}

// =====================================================================
extern "C" void kernel_launch(void* const* d_in, const int* in_sizes, int n_in,
                              void* d_out, int out_size)
{
    const float* x   = (const float*)d_in[0];
    const float* Wq  = (const float*)d_in[1];
    const float* Wk  = (const float*)d_in[2];
    const float* Wv  = (const float*)d_in[3];
    const float* rel = (const float*)d_in[4];
    const float* Wp  = (const float*)d_in[5];
    const float* bp  = (const float*)d_in[6];
    float* out = (float*)d_out;

    cudaFuncSetAttribute(qkv4_kernel,
                         cudaFuncAttributeMaxDynamicSharedMemorySize, QSM4);
    cudaFuncSetAttribute(proj2_kernel,
                         cudaFuncAttributeMaxDynamicSharedMemorySize, GSMEM);
    cudaFuncSetAttribute(attn5_kernel,
                         cudaFuncAttributeMaxDynamicSharedMemorySize, ASMEM5);

    split_wr_kernel<<<dim3(81, 5), 256>>>(Wq, Wk, Wv, Wp, rel);

    qkv4_kernel<<<MTOT / 128, 256, QSM4>>>(x);

    attn5_kernel<<<BB * NH, 256, ASMEM5>>>();

    proj2_kernel<<<MTOT / 128, 256, GSMEM>>>(bp, out);
}

// round 13
// speedup vs baseline: 1.2046x; 1.0249x over previous
#include <cstdint>
#include <cuda_runtime.h>
#include <cuda_bf16.h>

#define NH   6
#define HS   24
#define NE   144
#define TT   128
#define BB   256
#define MTOT (BB*TT)        // 32768 tokens

typedef __nv_bfloat16 bf16;

// ---------------- device scratch (allocation-free, bf16 hi/lo pairs) --------
__device__ bf16 g_qhi[MTOT*NE], g_qlo[MTOT*NE];
__device__ bf16 g_khi[MTOT*NE], g_klo[MTOT*NE];   // pre-scaled by 1/sqrt(hs)
__device__ bf16 g_vhi[MTOT*NE], g_vlo[MTOT*NE];
__device__ bf16 g_chi[MTOT*NE], g_clo[MTOT*NE];   // ctx, split
__device__ bf16 g_wthi[4*NE*NE], g_wtlo[4*NE*NE]; // W^T [n][k], q,k,v,proj
__device__ bf16 g_rhi[255*HS],   g_rlo[255*HS];   // rel_table split

// ---------------- helpers ----------------
__device__ __forceinline__ void mma_bf16(float c[4],
    uint32_t a0, uint32_t a1, uint32_t a2, uint32_t a3,
    uint32_t b0, uint32_t b1)
{
    asm volatile(
        "mma.sync.aligned.m16n8k16.row.col.f32.bf16.bf16.f32 "
        "{%0,%1,%2,%3}, {%4,%5,%6,%7}, {%8,%9}, {%0,%1,%2,%3};"
        : "+f"(c[0]), "+f"(c[1]), "+f"(c[2]), "+f"(c[3])
        : "r"(a0), "r"(a1), "r"(a2), "r"(a3), "r"(b0), "r"(b1));
}

__device__ __forceinline__ void split2(float v0, float v1, uint32_t& hi, uint32_t& lo)
{
    bf16 h0 = __float2bfloat16(v0), h1 = __float2bfloat16(v1);
    float r0 = v0 - __bfloat162float(h0), r1 = v1 - __bfloat162float(h1);
    hi = ((uint32_t)__bfloat16_as_ushort(h1) << 16) | __bfloat16_as_ushort(h0);
    lo = ((uint32_t)__bfloat16_as_ushort(__float2bfloat16(r1)) << 16)
       |  (uint32_t)__bfloat16_as_ushort(__float2bfloat16(r0));
}

// =====================================================================
// Setup: weight transpose+split and rel_table split (small)
// =====================================================================
__global__ __launch_bounds__(256) void split_wr_kernel(
    const float* __restrict__ Wq, const float* __restrict__ Wk,
    const float* __restrict__ Wv, const float* __restrict__ Wp,
    const float* __restrict__ rel)
{
    int m = blockIdx.y;
    int i = blockIdx.x * 256 + threadIdx.x;
    if (m < 4) {
        if (i >= NE * NE) return;
        const float* src = (m == 0) ? Wq : (m == 1) ? Wk : (m == 2) ? Wv : Wp;
        int k = i / NE, n = i - k * NE;
        float v = src[i];
        bf16 h = __float2bfloat16(v);
        g_wthi[m * NE * NE + n * NE + k] = h;
        g_wtlo[m * NE * NE + n * NE + k] = __float2bfloat16(v - __bfloat162float(h));
    } else {
        if (i >= 255 * HS) return;
        float v = rel[i];
        bf16 h = __float2bfloat16(v);
        g_rhi[i] = h;
        g_rlo[i] = __float2bfloat16(v - __bfloat162float(h));
    }
}

// =====================================================================
// qkv4: fused Q/K/V GEMM, A tile resident (split once), grid 256.
// smem: A_hi[128][152] | A_lo | B_hi[144][56] | B_lo   = 110080 B, 2 CTAs/SM
// =====================================================================
#define LDA4 152
#define LDS2 56
#define QSM4 (2*128*LDA4*2 + 2*144*LDS2*2)   // 110080

__global__ __launch_bounds__(256, 2) void qkv4_kernel(const float* __restrict__ x)
{
    extern __shared__ __align__(16) char smc[];
    bf16* A_hi = (bf16*)smc;                          // [128][152]
    bf16* A_lo = A_hi + 128 * LDA4;
    bf16* Bs_hi = A_lo + 128 * LDA4;                  // [144][56]
    bf16* Bs_lo = Bs_hi + 144 * LDS2;

    const int r0 = blockIdx.x * 128;
    const int tid = threadIdx.x;
    const int w = tid >> 5, lane = tid & 31, g = lane >> 2, t = lane & 3;
    const int mrow = (w & 3) * 32, ncol = (w >> 2) * 72;

    // ---- load + split A once (128 x 144 fp32 -> hi/lo bf16) ----
    for (int i = tid; i < 128 * 36; i += 256) {
        int r = i / 36, j = i - r * 36;
        float4 v = *(const float4*)&x[(r0 + r) * NE + j * 4];
        uint32_t h0, l0, h1, l1;
        split2(v.x, v.y, h0, l0);
        split2(v.z, v.w, h1, l1);
        *(uint32_t*)&A_hi[r * LDA4 + j * 4]     = h0;
        *(uint32_t*)&A_hi[r * LDA4 + j * 4 + 2] = h1;
        *(uint32_t*)&A_lo[r * LDA4 + j * 4]     = l0;
        *(uint32_t*)&A_lo[r * LDA4 + j * 4 + 2] = l1;
    }
    __syncthreads();

    #pragma unroll 1
    for (int z = 0; z < 3; ++z) {
        const bf16* Wthi = g_wthi + z * NE * NE;
        const bf16* Wtlo = g_wtlo + z * NE * NE;

        float acc[2][9][4];
        #pragma unroll
        for (int mt = 0; mt < 2; ++mt)
            #pragma unroll
            for (int nt = 0; nt < 9; ++nt)
                #pragma unroll
                for (int j = 0; j < 4; ++j) acc[mt][nt][j] = 0.f;

        #pragma unroll 1
        for (int kc = 0; kc < NE; kc += 48) {
            for (int i = tid; i < 144 * 6; i += 256) {
                int r = i / 6, j = i - r * 6;
                *(uint4*)&Bs_hi[r * LDS2 + j * 8] = *(const uint4*)&Wthi[r * NE + kc + j * 8];
                *(uint4*)&Bs_lo[r * LDS2 + j * 8] = *(const uint4*)&Wtlo[r * NE + kc + j * 8];
            }
            __syncthreads();

            #pragma unroll 1
            for (int p = 0; p < 3; ++p) {
                const bf16* Ap = (p == 1) ? A_lo : A_hi;
                const bf16* Bp = (p == 2) ? Bs_lo : Bs_hi;
                #pragma unroll
                for (int ks = 0; ks < 3; ++ks) {
                    const int ka = kc + ks * 16;     // absolute k into resident A
                    const int kb = ks * 16;          // local k into B chunk
                    uint32_t a[2][4];
                    #pragma unroll
                    for (int mt = 0; mt < 2; ++mt) {
                        const bf16* ab = Ap + (mrow + mt * 16 + g) * LDA4 + ka + 2 * t;
                        a[mt][0] = *(const uint32_t*)(ab);
                        a[mt][1] = *(const uint32_t*)(ab + 8 * LDA4);
                        a[mt][2] = *(const uint32_t*)(ab + 8);
                        a[mt][3] = *(const uint32_t*)(ab + 8 * LDA4 + 8);
                    }
                    #pragma unroll
                    for (int nt = 0; nt < 9; ++nt) {
                        const bf16* bb = Bp + (ncol + nt * 8 + g) * LDS2 + kb + 2 * t;
                        uint32_t b0 = *(const uint32_t*)(bb);
                        uint32_t b1 = *(const uint32_t*)(bb + 8);
                        mma_bf16(acc[0][nt], a[0][0], a[0][1], a[0][2], a[0][3], b0, b1);
                        mma_bf16(acc[1][nt], a[1][0], a[1][1], a[1][2], a[1][3], b0, b1);
                    }
                }
            }
            __syncthreads();
        }

        bf16* ohi = (z == 0) ? g_qhi : (z == 1) ? g_khi : g_vhi;
        bf16* olo = (z == 0) ? g_qlo : (z == 1) ? g_klo : g_vlo;
        const float sc = (z == 1) ? 0.2041241452319315f : 1.f;

        #pragma unroll
        for (int mt = 0; mt < 2; ++mt) {
            #pragma unroll
            for (int nt = 0; nt < 9; ++nt) {
                int row = r0 + mrow + mt * 16 + g;
                int col = ncol + nt * 8 + 2 * t;
                uint32_t h, l;
                split2(acc[mt][nt][0] * sc, acc[mt][nt][1] * sc, h, l);
                *(uint32_t*)&ohi[row * NE + col] = h;
                *(uint32_t*)&olo[row * NE + col] = l;
                split2(acc[mt][nt][2] * sc, acc[mt][nt][3] * sc, h, l);
                *(uint32_t*)&ohi[(row + 8) * NE + col] = h;
                *(uint32_t*)&olo[(row + 8) * NE + col] = l;
            }
        }
    }
}

// =====================================================================
// proj (R10-exact gemm2 core, validated 28.4us)
// =====================================================================
#define GSMEM ((128*LDS2 + 128*LDS2 + 144*LDS2 + 144*LDS2) * 2)   // 60928

__global__ __launch_bounds__(256, 2) void proj2_kernel(
    const float* __restrict__ bias, float* __restrict__ out)
{
    extern __shared__ __align__(16) char smc[];
    bf16* As_hi = (bf16*)smc;
    bf16* As_lo = As_hi + 128 * LDS2;
    bf16* Bs_hi = As_lo + 128 * LDS2;
    bf16* Bs_lo = Bs_hi + 144 * LDS2;

    const bf16* Ahig = g_chi;
    const bf16* Alog = g_clo;
    const bf16* Wthi = g_wthi + 3 * NE * NE;
    const bf16* Wtlo = g_wtlo + 3 * NE * NE;
    const int r0 = blockIdx.x * 128;

    const int tid = threadIdx.x;
    const int w = tid >> 5, lane = tid & 31, g = lane >> 2, t = lane & 3;
    const int mrow = (w & 3) * 32, ncol = (w >> 2) * 72;

    float acc[2][9][4];
    #pragma unroll
    for (int mt = 0; mt < 2; ++mt)
        #pragma unroll
        for (int nt = 0; nt < 9; ++nt)
            #pragma unroll
            for (int j = 0; j < 4; ++j) acc[mt][nt][j] = 0.f;

    #pragma unroll 1
    for (int kc = 0; kc < NE; kc += 48) {
        for (int i = tid; i < 128 * 6; i += 256) {
            int r = i / 6, j = i - r * 6;
            *(uint4*)&As_hi[r * LDS2 + j * 8] = *(const uint4*)&Ahig[(r0 + r) * NE + kc + j * 8];
            *(uint4*)&As_lo[r * LDS2 + j * 8] = *(const uint4*)&Alog[(r0 + r) * NE + kc + j * 8];
        }
        for (int i = tid; i < 144 * 6; i += 256) {
            int r = i / 6, j = i - r * 6;
            *(uint4*)&Bs_hi[r * LDS2 + j * 8] = *(const uint4*)&Wthi[r * NE + kc + j * 8];
            *(uint4*)&Bs_lo[r * LDS2 + j * 8] = *(const uint4*)&Wtlo[r * NE + kc + j * 8];
        }
        __syncthreads();

        #pragma unroll 1
        for (int p = 0; p < 3; ++p) {
            const bf16* Ap = (p == 1) ? As_lo : As_hi;
            const bf16* Bp = (p == 2) ? Bs_lo : Bs_hi;
            #pragma unroll
            for (int ks = 0; ks < 3; ++ks) {
                const int k0 = ks * 16;
                uint32_t a[2][4];
                #pragma unroll
                for (int mt = 0; mt < 2; ++mt) {
                    const bf16* ab = Ap + (mrow + mt * 16 + g) * LDS2 + k0 + 2 * t;
                    a[mt][0] = *(const uint32_t*)(ab);
                    a[mt][1] = *(const uint32_t*)(ab + 8 * LDS2);
                    a[mt][2] = *(const uint32_t*)(ab + 8);
                    a[mt][3] = *(const uint32_t*)(ab + 8 * LDS2 + 8);
                }
                #pragma unroll
                for (int nt = 0; nt < 9; ++nt) {
                    const bf16* bb = Bp + (ncol + nt * 8 + g) * LDS2 + k0 + 2 * t;
                    uint32_t b0 = *(const uint32_t*)(bb);
                    uint32_t b1 = *(const uint32_t*)(bb + 8);
                    mma_bf16(acc[0][nt], a[0][0], a[0][1], a[0][2], a[0][3], b0, b1);
                    mma_bf16(acc[1][nt], a[1][0], a[1][1], a[1][2], a[1][3], b0, b1);
                }
            }
        }
        __syncthreads();
    }

    #pragma unroll
    for (int mt = 0; mt < 2; ++mt) {
        #pragma unroll
        for (int nt = 0; nt < 9; ++nt) {
            int row = r0 + mrow + mt * 16 + g;
            int col = ncol + nt * 8 + 2 * t;
            float b0v = bias[col], b1v = bias[col + 1];
            out[row * NE + col]           = acc[mt][nt][0] + b0v;
            out[row * NE + col + 1]       = acc[mt][nt][1] + b1v;
            out[(row + 8) * NE + col]     = acc[mt][nt][2] + b0v;
            out[(row + 8) * NE + col + 1] = acc[mt][nt][3] + b1v;
        }
    }
}

// =====================================================================
// Attention v7: attn5 + triangular culling (warp-uniform early break).
// Warp w owns rows w*16..w*16+15 -> needs col-tile nt <= 2w+1, k-tile ks <= w.
// =====================================================================
#define VLD   136     // Vt row stride (bf16)
#define SLD   132     // P row stride (fp32)
#define ASMEM5 (128*SLD*4 + 2*24*VLD*2)   // 80640 B

__global__ __launch_bounds__(256, 2) void attn7_kernel()
{
    extern __shared__ __align__(16) char smc[];
    float* P   = (float*)smc;                       // [128][132] fp32
    bf16* Vthi = (bf16*)(smc + 128 * SLD * 4);      // [24][136]
    bf16* Vtlo = Vthi + 24 * VLD;

    const int bh = blockIdx.x;
    const int b = bh / NH, h = bh % NH;
    const int base = b * (TT * NE) + h * (TT * HS); // contiguous head chunk
    const int tid = threadIdx.x;

    {   // V transpose into smem
        const int row = tid >> 1, half = (tid & 1) * 12;
        const int src = base + row * HS + half;
        #pragma unroll
        for (int j = 0; j < 12; ++j) {
            Vthi[(half + j) * VLD + row] = g_vhi[src + j];
            Vtlo[(half + j) * VLD + row] = g_vlo[src + j];
        }
    }
    __syncthreads();   // the only block barrier

    const int w = tid >> 5, lane = tid & 31, g = lane >> 2, t = lane & 3;
    const int tr  = w * 16 + g;
    const int tr2 = tr + 8;
    const int ntmax = 2 * w + 1;      // last needed column tile (cols <= w*16+15)

    float acc[16][4];

    // ---- pass 1: acc = P = Q @ R^T (triangular: nt <= ntmax) ----
    #pragma unroll
    for (int nt = 0; nt < 16; ++nt)
        #pragma unroll
        for (int j = 0; j < 4; ++j) acc[nt][j] = 0.f;

    #pragma unroll 1
    for (int p = 0; p < 3; ++p) {
        const bf16* Ag = ((p == 1) ? g_qlo : g_qhi) + base;
        const bf16* Bg = ((p == 2) ? g_rlo : g_rhi) + 127 * HS;
        const bf16* ab = Ag + tr * HS + 2 * t;
        uint32_t a0 = *(const uint32_t*)(ab);
        uint32_t a1 = *(const uint32_t*)(ab + 8 * HS);
        uint32_t a2 = *(const uint32_t*)(ab + 8);
        uint32_t a3 = *(const uint32_t*)(ab + 8 * HS + 8);
        uint32_t a4 = *(const uint32_t*)(ab + 16);
        uint32_t a5 = *(const uint32_t*)(ab + 8 * HS + 16);
        #pragma unroll
        for (int nt = 0; nt < 16; ++nt) {
            if (nt > ntmax) break;
            const bf16* bb = Bg + (nt * 8 + g) * HS + 2 * t;
            uint32_t b0 = *(const uint32_t*)(bb);
            uint32_t b1 = *(const uint32_t*)(bb + 8);
            uint32_t b2 = *(const uint32_t*)(bb + 16);
            mma_bf16(acc[nt], a0, a1, a2, a3, b0, b1);
            mma_bf16(acc[nt], a4, a5, 0u, 0u, b2, 0u);
        }
    }
    #pragma unroll
    for (int nt = 0; nt < 16; ++nt) {
        if (nt > ntmax) break;
        *(float2*)&P[tr  * SLD + nt * 8 + 2 * t] = make_float2(acc[nt][0], acc[nt][1]);
        *(float2*)&P[tr2 * SLD + nt * 8 + 2 * t] = make_float2(acc[nt][2], acc[nt][3]);
    }
    __syncwarp();

    // ---- pass 2: acc = S = Q @ K'^T (triangular) ----
    #pragma unroll
    for (int nt = 0; nt < 16; ++nt)
        #pragma unroll
        for (int j = 0; j < 4; ++j) acc[nt][j] = 0.f;

    #pragma unroll 1
    for (int p = 0; p < 3; ++p) {
        const bf16* Ag = ((p == 1) ? g_qlo : g_qhi) + base;
        const bf16* Bg = ((p == 2) ? g_klo : g_khi) + base;
        const bf16* ab = Ag + tr * HS + 2 * t;
        uint32_t a0 = *(const uint32_t*)(ab);
        uint32_t a1 = *(const uint32_t*)(ab + 8 * HS);
        uint32_t a2 = *(const uint32_t*)(ab + 8);
        uint32_t a3 = *(const uint32_t*)(ab + 8 * HS + 8);
        uint32_t a4 = *(const uint32_t*)(ab + 16);
        uint32_t a5 = *(const uint32_t*)(ab + 8 * HS + 16);
        #pragma unroll
        for (int nt = 0; nt < 16; ++nt) {
            if (nt > ntmax) break;
            const bf16* bb = Bg + (nt * 8 + g) * HS + 2 * t;
            uint32_t b0 = *(const uint32_t*)(bb);
            uint32_t b1 = *(const uint32_t*)(bb + 8);
            uint32_t b2 = *(const uint32_t*)(bb + 16);
            mma_bf16(acc[nt], a0, a1, a2, a3, b0, b1);
            mma_bf16(acc[nt], a4, a5, 0u, 0u, b2, 0u);
        }
    }

    // ---- rel gather + causal mask (uncomputed tiles are 0 -> masked) ----
    #pragma unroll
    for (int nt = 0; nt < 16; ++nt) {
        int c = nt * 8 + 2 * t;
        acc[nt][0] = (c     <= tr ) ? acc[nt][0] + P[tr  * SLD + tr  - c    ] : -1e30f;
        acc[nt][1] = (c + 1 <= tr ) ? acc[nt][1] + P[tr  * SLD + tr  - c - 1] : -1e30f;
        acc[nt][2] = (c     <= tr2) ? acc[nt][2] + P[tr2 * SLD + tr2 - c    ] : -1e30f;
        acc[nt][3] = (c + 1 <= tr2) ? acc[nt][3] + P[tr2 * SLD + tr2 - c - 1] : -1e30f;
    }

    // ---- softmax in registers ----
    {
        float m1 = -1e30f, m2 = -1e30f;
        #pragma unroll
        for (int nt = 0; nt < 16; ++nt) {
            m1 = fmaxf(m1, fmaxf(acc[nt][0], acc[nt][1]));
            m2 = fmaxf(m2, fmaxf(acc[nt][2], acc[nt][3]));
        }
        m1 = fmaxf(m1, __shfl_xor_sync(0xffffffffu, m1, 1));
        m1 = fmaxf(m1, __shfl_xor_sync(0xffffffffu, m1, 2));
        m2 = fmaxf(m2, __shfl_xor_sync(0xffffffffu, m2, 1));
        m2 = fmaxf(m2, __shfl_xor_sync(0xffffffffu, m2, 2));
        float s1 = 0.f, s2 = 0.f;
        #pragma unroll
        for (int nt = 0; nt < 16; ++nt) {
            acc[nt][0] = __expf(acc[nt][0] - m1);  s1 += acc[nt][0];
            acc[nt][1] = __expf(acc[nt][1] - m1);  s1 += acc[nt][1];
            acc[nt][2] = __expf(acc[nt][2] - m2);  s2 += acc[nt][2];
            acc[nt][3] = __expf(acc[nt][3] - m2);  s2 += acc[nt][3];
        }
        s1 += __shfl_xor_sync(0xffffffffu, s1, 1);
        s1 += __shfl_xor_sync(0xffffffffu, s1, 2);
        s2 += __shfl_xor_sync(0xffffffffu, s2, 1);
        s2 += __shfl_xor_sync(0xffffffffu, s2, 2);
        float i1 = 1.0f / s1, i2 = 1.0f / s2;
        #pragma unroll
        for (int nt = 0; nt < 16; ++nt) {
            acc[nt][0] *= i1;  acc[nt][1] *= i1;
            acc[nt][2] *= i2;  acc[nt][3] *= i2;
        }
    }

    // ---- ctx = S @ V (triangular: k-tile ks <= w; S==0 beyond) ----
    {
        float cacc[3][4];
        #pragma unroll
        for (int nt = 0; nt < 3; ++nt)
            #pragma unroll
            for (int j = 0; j < 4; ++j) cacc[nt][j] = 0.f;

        #pragma unroll
        for (int ks = 0; ks < 8; ++ks) {
            if (ks > w) break;
            const int k0 = ks * 16;
            uint32_t ah0, al0, ah1, al1, ah2, al2, ah3, al3;
            split2(acc[2*ks][0],   acc[2*ks][1],   ah0, al0);
            split2(acc[2*ks][2],   acc[2*ks][3],   ah1, al1);
            split2(acc[2*ks+1][0], acc[2*ks+1][1], ah2, al2);
            split2(acc[2*ks+1][2], acc[2*ks+1][3], ah3, al3);
            #pragma unroll
            for (int nt = 0; nt < 3; ++nt) {
                const bf16* bhp = Vthi + (nt * 8 + g) * VLD + k0 + 2 * t;
                const bf16* blp = Vtlo + (nt * 8 + g) * VLD + k0 + 2 * t;
                uint32_t bh0 = *(const uint32_t*)(bhp);
                uint32_t bh1 = *(const uint32_t*)(bhp + 8);
                uint32_t bl0 = *(const uint32_t*)(blp);
                uint32_t bl1 = *(const uint32_t*)(blp + 8);
                mma_bf16(cacc[nt], ah0, ah1, ah2, ah3, bh0, bh1);
                mma_bf16(cacc[nt], al0, al1, al2, al3, bh0, bh1);
                mma_bf16(cacc[nt], ah0, ah1, ah2, ah3, bl0, bl1);
            }
        }

        #pragma unroll
        for (int nt = 0; nt < 3; ++nt) {
            int col = nt * 8 + 2 * t;
            int idx = b * (TT * NE) + tr * NE + h * HS + col;
            uint32_t hp, lp;
            split2(cacc[nt][0], cacc[nt][1], hp, lp);
            *(uint32_t*)&g_chi[idx] = hp;
            *(uint32_t*)&g_clo[idx] = lp;
            split2(cacc[nt][2], cacc[nt][3], hp, lp);
            *(uint32_t*)&g_chi[idx + 8 * NE] = hp;
            *(uint32_t*)&g_clo[idx + 8 * NE] = lp;
        }
    }
}

// =====================================================================
extern "C" void kernel_launch(void* const* d_in, const int* in_sizes, int n_in,
                              void* d_out, int out_size)
{
    const float* x   = (const float*)d_in[0];
    const float* Wq  = (const float*)d_in[1];
    const float* Wk  = (const float*)d_in[2];
    const float* Wv  = (const float*)d_in[3];
    const float* rel = (const float*)d_in[4];
    const float* Wp  = (const float*)d_in[5];
    const float* bp  = (const float*)d_in[6];
    float* out = (float*)d_out;

    cudaFuncSetAttribute(qkv4_kernel,
                         cudaFuncAttributeMaxDynamicSharedMemorySize, QSM4);
    cudaFuncSetAttribute(proj2_kernel,
                         cudaFuncAttributeMaxDynamicSharedMemorySize, GSMEM);
    cudaFuncSetAttribute(attn7_kernel,
                         cudaFuncAttributeMaxDynamicSharedMemorySize, ASMEM5);

    split_wr_kernel<<<dim3(81, 5), 256>>>(Wq, Wk, Wv, Wp, rel);

    qkv4_kernel<<<MTOT / 128, 256, QSM4>>>(x);

    attn7_kernel<<<BB * NH, 256, ASMEM5>>>();

    proj2_kernel<<<MTOT / 128, 256, GSMEM>>>(bp, out);
}

// round 14
// speedup vs baseline: 1.2524x; 1.0396x over previous
#include <cstdint>
#include <cuda_runtime.h>
#include <cuda_bf16.h>

#define NH   6
#define HS   24
#define NE   144
#define TT   128
#define BB   256
#define MTOT (BB*TT)        // 32768 tokens

typedef __nv_bfloat16 bf16;

// ---------------- device scratch (allocation-free, bf16 hi/lo pairs) --------
__device__ bf16 g_qhi[MTOT*NE], g_qlo[MTOT*NE];
__device__ bf16 g_khi[MTOT*NE], g_klo[MTOT*NE];   // pre-scaled by 1/sqrt(hs)
__device__ bf16 g_vhi[MTOT*NE], g_vlo[MTOT*NE];
__device__ bf16 g_chi[MTOT*NE], g_clo[MTOT*NE];   // ctx, split
__device__ bf16 g_wthi[4*NE*NE], g_wtlo[4*NE*NE]; // W^T [n][k], q,k,v,proj
__device__ bf16 g_rhi[255*HS],   g_rlo[255*HS];   // rel_table split

// ---------------- helpers ----------------
__device__ __forceinline__ void mma_bf16(float c[4],
    uint32_t a0, uint32_t a1, uint32_t a2, uint32_t a3,
    uint32_t b0, uint32_t b1)
{
    asm volatile(
        "mma.sync.aligned.m16n8k16.row.col.f32.bf16.bf16.f32 "
        "{%0,%1,%2,%3}, {%4,%5,%6,%7}, {%8,%9}, {%0,%1,%2,%3};"
        : "+f"(c[0]), "+f"(c[1]), "+f"(c[2]), "+f"(c[3])
        : "r"(a0), "r"(a1), "r"(a2), "r"(a3), "r"(b0), "r"(b1));
}

__device__ __forceinline__ void split2(float v0, float v1, uint32_t& hi, uint32_t& lo)
{
    bf16 h0 = __float2bfloat16(v0), h1 = __float2bfloat16(v1);
    float r0 = v0 - __bfloat162float(h0), r1 = v1 - __bfloat162float(h1);
    hi = ((uint32_t)__bfloat16_as_ushort(h1) << 16) | __bfloat16_as_ushort(h0);
    lo = ((uint32_t)__bfloat16_as_ushort(__float2bfloat16(r1)) << 16)
       |  (uint32_t)__bfloat16_as_ushort(__float2bfloat16(r0));
}

// =====================================================================
// Setup: weight transpose+split and rel_table split (small)
// =====================================================================
__global__ __launch_bounds__(256) void split_wr_kernel(
    const float* __restrict__ Wq, const float* __restrict__ Wk,
    const float* __restrict__ Wv, const float* __restrict__ Wp,
    const float* __restrict__ rel)
{
    int m = blockIdx.y;
    int i = blockIdx.x * 256 + threadIdx.x;
    if (m < 4) {
        if (i >= NE * NE) return;
        const float* src = (m == 0) ? Wq : (m == 1) ? Wk : (m == 2) ? Wv : Wp;
        int k = i / NE, n = i - k * NE;
        float v = src[i];
        bf16 h = __float2bfloat16(v);
        g_wthi[m * NE * NE + n * NE + k] = h;
        g_wtlo[m * NE * NE + n * NE + k] = __float2bfloat16(v - __bfloat162float(h));
    } else {
        if (i >= 255 * HS) return;
        float v = rel[i];
        bf16 h = __float2bfloat16(v);
        g_rhi[i] = h;
        g_rlo[i] = __float2bfloat16(v - __bfloat162float(h));
    }
}

// =====================================================================
// gemm5: A resident in smem (one barrier), B fragments from global,
// fused 3-term split per k-tile (bh/bl loaded once).
// smem: A_hi[128][152] | A_lo  = 77824 B -> 2 CTAs/SM.
// =====================================================================
#define LDA4 152
#define GSM5 (2*128*LDA4*2)   // 77824

// mainloop over one weight matrix: acc += A(128x144) @ W^T(144x144 rows=n)
__device__ __forceinline__ void gemm5_loop(
    const bf16* __restrict__ Asm_hi, const bf16* __restrict__ Asm_lo,
    const bf16* __restrict__ Wh, const bf16* __restrict__ Wl,
    float acc[2][9][4], int mrow, int ncol, int g, int t)
{
    #pragma unroll 1
    for (int ks = 0; ks < 9; ++ks) {
        const int k0 = ks * 16;
        uint32_t ah[2][4], al[2][4];
        #pragma unroll
        for (int mt = 0; mt < 2; ++mt) {
            const bf16* abh = Asm_hi + (mrow + mt * 16 + g) * LDA4 + k0 + 2 * t;
            ah[mt][0] = *(const uint32_t*)(abh);
            ah[mt][1] = *(const uint32_t*)(abh + 8 * LDA4);
            ah[mt][2] = *(const uint32_t*)(abh + 8);
            ah[mt][3] = *(const uint32_t*)(abh + 8 * LDA4 + 8);
            const bf16* abl = Asm_lo + (mrow + mt * 16 + g) * LDA4 + k0 + 2 * t;
            al[mt][0] = *(const uint32_t*)(abl);
            al[mt][1] = *(const uint32_t*)(abl + 8 * LDA4);
            al[mt][2] = *(const uint32_t*)(abl + 8);
            al[mt][3] = *(const uint32_t*)(abl + 8 * LDA4 + 8);
        }
        #pragma unroll
        for (int nt = 0; nt < 9; ++nt) {
            const int nrow = (ncol + nt * 8 + g) * NE + k0 + 2 * t;
            uint32_t bh0 = *(const uint32_t*)(Wh + nrow);
            uint32_t bh1 = *(const uint32_t*)(Wh + nrow + 8);
            uint32_t bl0 = *(const uint32_t*)(Wl + nrow);
            uint32_t bl1 = *(const uint32_t*)(Wl + nrow + 8);
            #pragma unroll
            for (int mt = 0; mt < 2; ++mt) {
                mma_bf16(acc[mt][nt], ah[mt][0], ah[mt][1], ah[mt][2], ah[mt][3], bh0, bh1);
                mma_bf16(acc[mt][nt], al[mt][0], al[mt][1], al[mt][2], al[mt][3], bh0, bh1);
                mma_bf16(acc[mt][nt], ah[mt][0], ah[mt][1], ah[mt][2], ah[mt][3], bl0, bl1);
            }
        }
    }
}

__global__ __launch_bounds__(256, 2) void qkv5_kernel(const float* __restrict__ x)
{
    extern __shared__ __align__(16) char smc[];
    bf16* A_hi = (bf16*)smc;                          // [128][152]
    bf16* A_lo = A_hi + 128 * LDA4;

    const int r0 = blockIdx.x * 128;
    const int tid = threadIdx.x;
    const int w = tid >> 5, lane = tid & 31, g = lane >> 2, t = lane & 3;
    const int mrow = (w & 3) * 32, ncol = (w >> 2) * 72;

    // ---- load + split A once ----
    for (int i = tid; i < 128 * 36; i += 256) {
        int r = i / 36, j = i - r * 36;
        float4 v = *(const float4*)&x[(r0 + r) * NE + j * 4];
        uint32_t h0, l0, h1, l1;
        split2(v.x, v.y, h0, l0);
        split2(v.z, v.w, h1, l1);
        *(uint32_t*)&A_hi[r * LDA4 + j * 4]     = h0;
        *(uint32_t*)&A_hi[r * LDA4 + j * 4 + 2] = h1;
        *(uint32_t*)&A_lo[r * LDA4 + j * 4]     = l0;
        *(uint32_t*)&A_lo[r * LDA4 + j * 4 + 2] = l1;
    }
    __syncthreads();   // the only barrier

    #pragma unroll 1
    for (int z = 0; z < 3; ++z) {
        float acc[2][9][4];
        #pragma unroll
        for (int mt = 0; mt < 2; ++mt)
            #pragma unroll
            for (int nt = 0; nt < 9; ++nt)
                #pragma unroll
                for (int j = 0; j < 4; ++j) acc[mt][nt][j] = 0.f;

        gemm5_loop(A_hi, A_lo, g_wthi + z * NE * NE, g_wtlo + z * NE * NE,
                   acc, mrow, ncol, g, t);

        bf16* ohi = (z == 0) ? g_qhi : (z == 1) ? g_khi : g_vhi;
        bf16* olo = (z == 0) ? g_qlo : (z == 1) ? g_klo : g_vlo;
        const float sc = (z == 1) ? 0.2041241452319315f : 1.f;

        #pragma unroll
        for (int mt = 0; mt < 2; ++mt) {
            #pragma unroll
            for (int nt = 0; nt < 9; ++nt) {
                int row = r0 + mrow + mt * 16 + g;
                int col = ncol + nt * 8 + 2 * t;
                uint32_t h, l;
                split2(acc[mt][nt][0] * sc, acc[mt][nt][1] * sc, h, l);
                *(uint32_t*)&ohi[row * NE + col] = h;
                *(uint32_t*)&olo[row * NE + col] = l;
                split2(acc[mt][nt][2] * sc, acc[mt][nt][3] * sc, h, l);
                *(uint32_t*)&ohi[(row + 8) * NE + col] = h;
                *(uint32_t*)&olo[(row + 8) * NE + col] = l;
            }
        }
    }
}

__global__ __launch_bounds__(256, 2) void proj5_kernel(
    const float* __restrict__ bias, float* __restrict__ out)
{
    extern __shared__ __align__(16) char smc[];
    bf16* A_hi = (bf16*)smc;                          // [128][152]
    bf16* A_lo = A_hi + 128 * LDA4;

    const int r0 = blockIdx.x * 128;
    const int tid = threadIdx.x;
    const int w = tid >> 5, lane = tid & 31, g = lane >> 2, t = lane & 3;
    const int mrow = (w & 3) * 32, ncol = (w >> 2) * 72;

    // ---- copy pre-split ctx A once (hi/lo, 18 uint4 per row) ----
    for (int i = tid; i < 128 * 18; i += 256) {
        int r = i / 18, j = i - r * 18;
        *(uint4*)&A_hi[r * LDA4 + j * 8] = *(const uint4*)&g_chi[(r0 + r) * NE + j * 8];
        *(uint4*)&A_lo[r * LDA4 + j * 8] = *(const uint4*)&g_clo[(r0 + r) * NE + j * 8];
    }
    __syncthreads();   // the only barrier

    float acc[2][9][4];
    #pragma unroll
    for (int mt = 0; mt < 2; ++mt)
        #pragma unroll
        for (int nt = 0; nt < 9; ++nt)
            #pragma unroll
            for (int j = 0; j < 4; ++j) acc[mt][nt][j] = 0.f;

    gemm5_loop(A_hi, A_lo, g_wthi + 3 * NE * NE, g_wtlo + 3 * NE * NE,
               acc, mrow, ncol, g, t);

    #pragma unroll
    for (int mt = 0; mt < 2; ++mt) {
        #pragma unroll
        for (int nt = 0; nt < 9; ++nt) {
            int row = r0 + mrow + mt * 16 + g;
            int col = ncol + nt * 8 + 2 * t;
            float b0v = bias[col], b1v = bias[col + 1];
            out[row * NE + col]           = acc[mt][nt][0] + b0v;
            out[row * NE + col + 1]       = acc[mt][nt][1] + b1v;
            out[(row + 8) * NE + col]     = acc[mt][nt][2] + b0v;
            out[(row + 8) * NE + col + 1] = acc[mt][nt][3] + b1v;
        }
    }
}

// =====================================================================
// Attention v7 (R13-exact): triangular culling, register-resident S.
// =====================================================================
#define VLD   136     // Vt row stride (bf16)
#define SLD   132     // P row stride (fp32)
#define ASMEM5 (128*SLD*4 + 2*24*VLD*2)   // 80640 B

__global__ __launch_bounds__(256, 2) void attn7_kernel()
{
    extern __shared__ __align__(16) char smc[];
    float* P   = (float*)smc;                       // [128][132] fp32
    bf16* Vthi = (bf16*)(smc + 128 * SLD * 4);      // [24][136]
    bf16* Vtlo = Vthi + 24 * VLD;

    const int bh = blockIdx.x;
    const int b = bh / NH, h = bh % NH;
    const int base = b * (TT * NE) + h * (TT * HS); // contiguous head chunk
    const int tid = threadIdx.x;

    {   // V transpose into smem
        const int row = tid >> 1, half = (tid & 1) * 12;
        const int src = base + row * HS + half;
        #pragma unroll
        for (int j = 0; j < 12; ++j) {
            Vthi[(half + j) * VLD + row] = g_vhi[src + j];
            Vtlo[(half + j) * VLD + row] = g_vlo[src + j];
        }
    }
    __syncthreads();   // the only block barrier

    const int w = tid >> 5, lane = tid & 31, g = lane >> 2, t = lane & 3;
    const int tr  = w * 16 + g;
    const int tr2 = tr + 8;
    const int ntmax = 2 * w + 1;

    float acc[16][4];

    // ---- pass 1: acc = P = Q @ R^T (triangular) ----
    #pragma unroll
    for (int nt = 0; nt < 16; ++nt)
        #pragma unroll
        for (int j = 0; j < 4; ++j) acc[nt][j] = 0.f;

    #pragma unroll 1
    for (int p = 0; p < 3; ++p) {
        const bf16* Ag = ((p == 1) ? g_qlo : g_qhi) + base;
        const bf16* Bg = ((p == 2) ? g_rlo : g_rhi) + 127 * HS;
        const bf16* ab = Ag + tr * HS + 2 * t;
        uint32_t a0 = *(const uint32_t*)(ab);
        uint32_t a1 = *(const uint32_t*)(ab + 8 * HS);
        uint32_t a2 = *(const uint32_t*)(ab + 8);
        uint32_t a3 = *(const uint32_t*)(ab + 8 * HS + 8);
        uint32_t a4 = *(const uint32_t*)(ab + 16);
        uint32_t a5 = *(const uint32_t*)(ab + 8 * HS + 16);
        #pragma unroll
        for (int nt = 0; nt < 16; ++nt) {
            if (nt > ntmax) break;
            const bf16* bb = Bg + (nt * 8 + g) * HS + 2 * t;
            uint32_t b0 = *(const uint32_t*)(bb);
            uint32_t b1 = *(const uint32_t*)(bb + 8);
            uint32_t b2 = *(const uint32_t*)(bb + 16);
            mma_bf16(acc[nt], a0, a1, a2, a3, b0, b1);
            mma_bf16(acc[nt], a4, a5, 0u, 0u, b2, 0u);
        }
    }
    #pragma unroll
    for (int nt = 0; nt < 16; ++nt) {
        if (nt > ntmax) break;
        *(float2*)&P[tr  * SLD + nt * 8 + 2 * t] = make_float2(acc[nt][0], acc[nt][1]);
        *(float2*)&P[tr2 * SLD + nt * 8 + 2 * t] = make_float2(acc[nt][2], acc[nt][3]);
    }
    __syncwarp();

    // ---- pass 2: acc = S = Q @ K'^T (triangular) ----
    #pragma unroll
    for (int nt = 0; nt < 16; ++nt)
        #pragma unroll
        for (int j = 0; j < 4; ++j) acc[nt][j] = 0.f;

    #pragma unroll 1
    for (int p = 0; p < 3; ++p) {
        const bf16* Ag = ((p == 1) ? g_qlo : g_qhi) + base;
        const bf16* Bg = ((p == 2) ? g_klo : g_khi) + base;
        const bf16* ab = Ag + tr * HS + 2 * t;
        uint32_t a0 = *(const uint32_t*)(ab);
        uint32_t a1 = *(const uint32_t*)(ab + 8 * HS);
        uint32_t a2 = *(const uint32_t*)(ab + 8);
        uint32_t a3 = *(const uint32_t*)(ab + 8 * HS + 8);
        uint32_t a4 = *(const uint32_t*)(ab + 16);
        uint32_t a5 = *(const uint32_t*)(ab + 8 * HS + 16);
        #pragma unroll
        for (int nt = 0; nt < 16; ++nt) {
            if (nt > ntmax) break;
            const bf16* bb = Bg + (nt * 8 + g) * HS + 2 * t;
            uint32_t b0 = *(const uint32_t*)(bb);
            uint32_t b1 = *(const uint32_t*)(bb + 8);
            uint32_t b2 = *(const uint32_t*)(bb + 16);
            mma_bf16(acc[nt], a0, a1, a2, a3, b0, b1);
            mma_bf16(acc[nt], a4, a5, 0u, 0u, b2, 0u);
        }
    }

    // ---- rel gather + causal mask ----
    #pragma unroll
    for (int nt = 0; nt < 16; ++nt) {
        int c = nt * 8 + 2 * t;
        acc[nt][0] = (c     <= tr ) ? acc[nt][0] + P[tr  * SLD + tr  - c    ] : -1e30f;
        acc[nt][1] = (c + 1 <= tr ) ? acc[nt][1] + P[tr  * SLD + tr  - c - 1] : -1e30f;
        acc[nt][2] = (c     <= tr2) ? acc[nt][2] + P[tr2 * SLD + tr2 - c    ] : -1e30f;
        acc[nt][3] = (c + 1 <= tr2) ? acc[nt][3] + P[tr2 * SLD + tr2 - c - 1] : -1e30f;
    }

    // ---- softmax in registers ----
    {
        float m1 = -1e30f, m2 = -1e30f;
        #pragma unroll
        for (int nt = 0; nt < 16; ++nt) {
            m1 = fmaxf(m1, fmaxf(acc[nt][0], acc[nt][1]));
            m2 = fmaxf(m2, fmaxf(acc[nt][2], acc[nt][3]));
        }
        m1 = fmaxf(m1, __shfl_xor_sync(0xffffffffu, m1, 1));
        m1 = fmaxf(m1, __shfl_xor_sync(0xffffffffu, m1, 2));
        m2 = fmaxf(m2, __shfl_xor_sync(0xffffffffu, m2, 1));
        m2 = fmaxf(m2, __shfl_xor_sync(0xffffffffu, m2, 2));
        float s1 = 0.f, s2 = 0.f;
        #pragma unroll
        for (int nt = 0; nt < 16; ++nt) {
            acc[nt][0] = __expf(acc[nt][0] - m1);  s1 += acc[nt][0];
            acc[nt][1] = __expf(acc[nt][1] - m1);  s1 += acc[nt][1];
            acc[nt][2] = __expf(acc[nt][2] - m2);  s2 += acc[nt][2];
            acc[nt][3] = __expf(acc[nt][3] - m2);  s2 += acc[nt][3];
        }
        s1 += __shfl_xor_sync(0xffffffffu, s1, 1);
        s1 += __shfl_xor_sync(0xffffffffu, s1, 2);
        s2 += __shfl_xor_sync(0xffffffffu, s2, 1);
        s2 += __shfl_xor_sync(0xffffffffu, s2, 2);
        float i1 = 1.0f / s1, i2 = 1.0f / s2;
        #pragma unroll
        for (int nt = 0; nt < 16; ++nt) {
            acc[nt][0] *= i1;  acc[nt][1] *= i1;
            acc[nt][2] *= i2;  acc[nt][3] *= i2;
        }
    }

    // ---- ctx = S @ V (triangular: ks <= w) ----
    {
        float cacc[3][4];
        #pragma unroll
        for (int nt = 0; nt < 3; ++nt)
            #pragma unroll
            for (int j = 0; j < 4; ++j) cacc[nt][j] = 0.f;

        #pragma unroll
        for (int ks = 0; ks < 8; ++ks) {
            if (ks > w) break;
            const int k0 = ks * 16;
            uint32_t ah0, al0, ah1, al1, ah2, al2, ah3, al3;
            split2(acc[2*ks][0],   acc[2*ks][1],   ah0, al0);
            split2(acc[2*ks][2],   acc[2*ks][3],   ah1, al1);
            split2(acc[2*ks+1][0], acc[2*ks+1][1], ah2, al2);
            split2(acc[2*ks+1][2], acc[2*ks+1][3], ah3, al3);
            #pragma unroll
            for (int nt = 0; nt < 3; ++nt) {
                const bf16* bhp = Vthi + (nt * 8 + g) * VLD + k0 + 2 * t;
                const bf16* blp = Vtlo + (nt * 8 + g) * VLD + k0 + 2 * t;
                uint32_t bh0 = *(const uint32_t*)(bhp);
                uint32_t bh1 = *(const uint32_t*)(bhp + 8);
                uint32_t bl0 = *(const uint32_t*)(blp);
                uint32_t bl1 = *(const uint32_t*)(blp + 8);
                mma_bf16(cacc[nt], ah0, ah1, ah2, ah3, bh0, bh1);
                mma_bf16(cacc[nt], al0, al1, al2, al3, bh0, bh1);
                mma_bf16(cacc[nt], ah0, ah1, ah2, ah3, bl0, bl1);
            }
        }

        #pragma unroll
        for (int nt = 0; nt < 3; ++nt) {
            int col = nt * 8 + 2 * t;
            int idx = b * (TT * NE) + tr * NE + h * HS + col;
            uint32_t hp, lp;
            split2(cacc[nt][0], cacc[nt][1], hp, lp);
            *(uint32_t*)&g_chi[idx] = hp;
            *(uint32_t*)&g_clo[idx] = lp;
            split2(cacc[nt][2], cacc[nt][3], hp, lp);
            *(uint32_t*)&g_chi[idx + 8 * NE] = hp;
            *(uint32_t*)&g_clo[idx + 8 * NE] = lp;
        }
    }
}

// =====================================================================
extern "C" void kernel_launch(void* const* d_in, const int* in_sizes, int n_in,
                              void* d_out, int out_size)
{
    const float* x   = (const float*)d_in[0];
    const float* Wq  = (const float*)d_in[1];
    const float* Wk  = (const float*)d_in[2];
    const float* Wv  = (const float*)d_in[3];
    const float* rel = (const float*)d_in[4];
    const float* Wp  = (const float*)d_in[5];
    const float* bp  = (const float*)d_in[6];
    float* out = (float*)d_out;

    cudaFuncSetAttribute(qkv5_kernel,
                         cudaFuncAttributeMaxDynamicSharedMemorySize, GSM5);
    cudaFuncSetAttribute(proj5_kernel,
                         cudaFuncAttributeMaxDynamicSharedMemorySize, GSM5);
    cudaFuncSetAttribute(attn7_kernel,
                         cudaFuncAttributeMaxDynamicSharedMemorySize, ASMEM5);

    split_wr_kernel<<<dim3(81, 5), 256>>>(Wq, Wk, Wv, Wp, rel);

    qkv5_kernel<<<MTOT / 128, 256, GSM5>>>(x);

    attn7_kernel<<<BB * NH, 256, ASMEM5>>>();

    proj5_kernel<<<MTOT / 128, 256, GSM5>>>(bp, out);
}